// round 2
// baseline (speedup 1.0000x reference)
#include <cuda_runtime.h>
#include <cstdint>
#include <cstddef>

// Problem constants
#define NF   131072
#define INS  256
#define HID  1024
#define OUTS 256
#define NE   16
#define TM   64      // tokens per CTA tile
#define HC   64      // hidden chunk
#define GRID (NF/TM + NE)   // 2064: upper bound on sum of per-expert tile counts

typedef unsigned long long u64;

// Routing scratch (device globals: no allocation allowed)
__device__ int g_cnt[NE];
__device__ int g_off[NE + 1];
__device__ int g_cur[NE];
__device__ int g_tile[NE + 1];
__device__ int g_perm[NF];
__device__ int g_ids_is64;

// ---------------- f32x2 helpers (sm_100+ packed fp32 pipe) ----------------
__device__ __forceinline__ u64 pk2(float lo, float hi) {
    u64 d; asm("mov.b64 %0, {%1, %2};" : "=l"(d) : "f"(lo), "f"(hi)); return d;
}
__device__ __forceinline__ float2 unpk(u64 d) {
    float2 r; asm("mov.b64 {%0, %1}, %2;" : "=f"(r.x), "=f"(r.y) : "l"(d)); return r;
}
__device__ __forceinline__ void fma2(u64& c, u64 a, u64 b) {
    asm("fma.rn.f32x2 %0, %1, %2, %0;" : "+l"(c) : "l"(a), "l"(b));
}

// ---------------- id dtype probe ----------------
// If ids really are int64, every value is in [0,16). If they are int32,
// a 64-bit read combines two ids: value = lo + hi*2^32 with hi in [0,16),
// so some sampled value exceeds 15 with overwhelming probability.
__global__ void k_detect(const long long* __restrict__ ids) {
    __shared__ int bad;
    if (threadIdx.x == 0) bad = 0;
    __syncthreads();
    for (int i = threadIdx.x; i < 4096; i += 256) {
        unsigned long long v = (unsigned long long)ids[i];
        if (v > 15ULL) bad = 1;
    }
    __syncthreads();
    if (threadIdx.x == 0) g_ids_is64 = bad ? 0 : 1;
}

__device__ __forceinline__ int get_id(const void* ids, int i, int is64) {
    int e = is64 ? (int)((const long long*)ids)[i] : ((const int*)ids)[i];
    return e & 15;
}

// ---------------- routing ----------------
__global__ void k_zero() {
    if (threadIdx.x < NE) g_cnt[threadIdx.x] = 0;
}

__global__ void k_count(const void* __restrict__ ids) {
    __shared__ int h[NE];
    int tid = threadIdx.x;
    if (tid < NE) h[tid] = 0;
    __syncthreads();
    int is64 = g_ids_is64;
    int base = blockIdx.x * 512;
    atomicAdd(&h[get_id(ids, base + tid, is64)], 1);
    atomicAdd(&h[get_id(ids, base + 256 + tid, is64)], 1);
    __syncthreads();
    if (tid < NE) atomicAdd(&g_cnt[tid], h[tid]);
}

__global__ void k_scan() {
    if (threadIdx.x == 0) {
        int o = 0, t = 0;
        for (int e = 0; e < NE; e++) {
            g_off[e] = o; g_cur[e] = o; g_tile[e] = t;
            o += g_cnt[e];
            t += (g_cnt[e] + TM - 1) / TM;
        }
        g_off[NE] = o; g_tile[NE] = t;
    }
}

__global__ void k_scatter(const void* __restrict__ ids) {
    __shared__ int h[NE], bm[NE];
    int tid = threadIdx.x;
    if (tid < NE) h[tid] = 0;
    __syncthreads();
    int is64 = g_ids_is64;
    int base = blockIdx.x * 512;
    int e0 = get_id(ids, base + tid, is64);
    int e1 = get_id(ids, base + 256 + tid, is64);
    atomicAdd(&h[e0], 1);
    atomicAdd(&h[e1], 1);
    __syncthreads();
    if (tid < NE) { bm[tid] = atomicAdd(&g_cur[tid], h[tid]); h[tid] = 0; }
    __syncthreads();
    int r0 = atomicAdd(&h[e0], 1); g_perm[bm[e0] + r0] = base + tid;
    int r1 = atomicAdd(&h[e1], 1); g_perm[bm[e1] + r1] = base + 256 + tid;
}

// ---------------- fused expert MLP ----------------
// SMEM layout (all dynamic):
//   xs2  [128 kp][64 t]   u64  : x token pairs along K         (65536 B)
//   w1t  [128 kp][64 j]   u64  : W1 chunk, transposed, K-pairs (65536 B)
//   hs2  [64 t][65]       u64  : relu(h) duplicated (h,h)      (33280 B)
//   w2s  [64 k][256 c]    f32  : W2 chunk, natural layout      (65536 B)
//   toks [64]             int                                  (256 B)
#define SMEM_BYTES (8192*8 + 8192*8 + 64*65*8 + HC*OUTS*4 + TM*4 + 192)

__global__ void __launch_bounds__(256, 1)
k_moe(const float* __restrict__ X,  const float* __restrict__ W1,
      const float* __restrict__ B1, const float* __restrict__ W2,
      const float* __restrict__ B2, float* __restrict__ Y)
{
    extern __shared__ u64 sm[];
    u64*   xs2 = sm;                       // kp*64 + t
    u64*   w1t = sm + 8192;                // kp*64 + j
    u64*   hs2 = sm + 16384;               // t*65 + k
    float* w2s = (float*)(sm + 16384 + 64*65);  // k*256 + c
    int*   toks = (int*)(w2s + HC*OUTS);

    int bid = blockIdx.x;
    if (bid >= g_tile[NE]) return;
    int e = 0;
    while (bid >= g_tile[e + 1]) e++;
    int goff = g_off[e];
    int cnt  = g_off[e + 1] - goff;
    int t0   = (bid - g_tile[e]) * TM;
    int vcnt = min(TM, cnt - t0);

    int tid = threadIdx.x;
    if (tid < TM) {
        int slot = t0 + tid;
        if (slot >= cnt) slot = cnt - 1;   // duplicate-pad tail tile (stores masked later)
        toks[tid] = g_perm[goff + slot];
    }
    __syncthreads();

    // Load x tile transposed into K-pair layout: xs2[kp][t] = (x[t][2kp], x[t][2kp+1])
    {
        int t = tid >> 2, s = tid & 3;
        const float* xr = X + (size_t)toks[t] * INS + s * 64;
        #pragma unroll
        for (int q = 0; q < 32; q++) {
            float2 v = *(const float2*)(xr + 2 * q);
            xs2[(s * 32 + q) * 64 + t] = pk2(v.x, v.y);
        }
    }

    const float* w1e = W1 + (size_t)e * INS * HID;
    const float* w2e = W2 + (size_t)e * HID * OUTS;
    const float* b1e = B1 + (size_t)e * HID;
    const float* b2e = B2 + (size_t)e * OUTS;

    int tt = tid & 15, ct = tid >> 4;      // phase A: 4x4 tile (tokens interleaved by 16)
    int cc = tid & 31, tb = tid >> 5;      // phase B: 8 tok x 8 col tile

    u64 yacc[8][4];
    #pragma unroll
    for (int i = 0; i < 8; i++)
        #pragma unroll
        for (int j = 0; j < 4; j++) yacc[i][j] = 0ULL;

    for (int h0 = 0; h0 < HID; h0 += HC) {
        __syncthreads();   // previous phase-B reads of w2s/hs2 done; xs2 ready (1st iter)

        // Load W1 chunk transposed, K-paired: w1t[kp][j] = (W1[2kp][h0+j], W1[2kp+1][h0+j])
        for (int idx = tid; idx < 128 * 64; idx += 256) {
            int j = idx & 63, kp = idx >> 6;
            float lo = w1e[(size_t)(2 * kp)     * HID + h0 + j];
            float hi = w1e[(size_t)(2 * kp + 1) * HID + h0 + j];
            w1t[kp * 64 + j] = pk2(lo, hi);
        }
        // Load W2 chunk natural layout: w2s[k][c]
        for (int idx = tid; idx < HC * OUTS; idx += 256) {
            int c = idx & 255, k = idx >> 8;
            w2s[k * OUTS + c] = w2e[(size_t)(h0 + k) * OUTS + c];
        }
        __syncthreads();

        // ---- Phase A: h = x @ W1chunk, pairs along K, 64x64 output ----
        u64 acc[4][4];
        #pragma unroll
        for (int i = 0; i < 4; i++)
            #pragma unroll
            for (int j = 0; j < 4; j++) acc[i][j] = 0ULL;

        #pragma unroll 8
        for (int kp = 0; kp < 128; kp++) {
            u64 a0 = xs2[kp * 64 + tt];
            u64 a1 = xs2[kp * 64 + tt + 16];
            u64 a2 = xs2[kp * 64 + tt + 32];
            u64 a3 = xs2[kp * 64 + tt + 48];
            ulonglong2 bx = *(const ulonglong2*)&w1t[kp * 64 + ct * 4];
            ulonglong2 by = *(const ulonglong2*)&w1t[kp * 64 + ct * 4 + 2];
            fma2(acc[0][0], a0, bx.x); fma2(acc[0][1], a0, bx.y);
            fma2(acc[0][2], a0, by.x); fma2(acc[0][3], a0, by.y);
            fma2(acc[1][0], a1, bx.x); fma2(acc[1][1], a1, bx.y);
            fma2(acc[1][2], a1, by.x); fma2(acc[1][3], a1, by.y);
            fma2(acc[2][0], a2, bx.x); fma2(acc[2][1], a2, bx.y);
            fma2(acc[2][2], a2, by.x); fma2(acc[2][3], a2, by.y);
            fma2(acc[3][0], a3, bx.x); fma2(acc[3][1], a3, bx.y);
            fma2(acc[3][2], a3, by.x); fma2(acc[3][3], a3, by.y);
        }

        // Epilogue A: fold K-pair, +b1, relu, store duplicated (h,h) for phase B
        #pragma unroll
        for (int i = 0; i < 4; i++) {
            int t = tt + 16 * i;
            #pragma unroll
            for (int j = 0; j < 4; j++) {
                float2 p = unpk(acc[i][j]);
                float hv = p.x + p.y + b1e[h0 + ct * 4 + j];
                hv = fmaxf(hv, 0.0f);
                hs2[t * 65 + ct * 4 + j] = pk2(hv, hv);
            }
        }
        __syncthreads();

        // ---- Phase B: y += relu(h) @ W2chunk, pairs along columns ----
        #pragma unroll 8
        for (int k = 0; k < HC; k++) {
            u64 a0 = hs2[(tb * 8 + 0) * 65 + k];
            u64 a1 = hs2[(tb * 8 + 1) * 65 + k];
            u64 a2 = hs2[(tb * 8 + 2) * 65 + k];
            u64 a3 = hs2[(tb * 8 + 3) * 65 + k];
            u64 a4 = hs2[(tb * 8 + 4) * 65 + k];
            u64 a5 = hs2[(tb * 8 + 5) * 65 + k];
            u64 a6 = hs2[(tb * 8 + 6) * 65 + k];
            u64 a7 = hs2[(tb * 8 + 7) * 65 + k];
            const u64* brow = (const u64*)(w2s + k * OUTS + cc * 8);
            ulonglong2 bA = *(const ulonglong2*)brow;
            ulonglong2 bB = *(const ulonglong2*)(brow + 2);
            fma2(yacc[0][0], a0, bA.x); fma2(yacc[0][1], a0, bA.y); fma2(yacc[0][2], a0, bB.x); fma2(yacc[0][3], a0, bB.y);
            fma2(yacc[1][0], a1, bA.x); fma2(yacc[1][1], a1, bA.y); fma2(yacc[1][2], a1, bB.x); fma2(yacc[1][3], a1, bB.y);
            fma2(yacc[2][0], a2, bA.x); fma2(yacc[2][1], a2, bA.y); fma2(yacc[2][2], a2, bB.x); fma2(yacc[2][3], a2, bB.y);
            fma2(yacc[3][0], a3, bA.x); fma2(yacc[3][1], a3, bA.y); fma2(yacc[3][2], a3, bB.x); fma2(yacc[3][3], a3, bB.y);
            fma2(yacc[4][0], a4, bA.x); fma2(yacc[4][1], a4, bA.y); fma2(yacc[4][2], a4, bB.x); fma2(yacc[4][3], a4, bB.y);
            fma2(yacc[5][0], a5, bA.x); fma2(yacc[5][1], a5, bA.y); fma2(yacc[5][2], a5, bB.x); fma2(yacc[5][3], a5, bB.y);
            fma2(yacc[6][0], a6, bA.x); fma2(yacc[6][1], a6, bA.y); fma2(yacc[6][2], a6, bB.x); fma2(yacc[6][3], a6, bB.y);
            fma2(yacc[7][0], a7, bA.x); fma2(yacc[7][1], a7, bA.y); fma2(yacc[7][2], a7, bB.x); fma2(yacc[7][3], a7, bB.y);
        }
    }

    // Final epilogue: +b2, scatter-store valid tokens
    #pragma unroll
    for (int i = 0; i < 8; i++) {
        int slot = tb * 8 + i;
        if (slot < vcnt) {
            float* yr = Y + (size_t)toks[slot] * OUTS + cc * 8;
            #pragma unroll
            for (int jp = 0; jp < 4; jp++) {
                float2 p = unpk(yacc[i][jp]);
                p.x += b2e[cc * 8 + 2 * jp];
                p.y += b2e[cc * 8 + 2 * jp + 1];
                *(float2*)(yr + 2 * jp) = p;
            }
        }
    }
}

// ---------------- launch ----------------
extern "C" void kernel_launch(void* const* d_in, const int* in_sizes, int n_in,
                              void* d_out, int out_size)
{
    (void)out_size;
    // Resolve inputs by element count (robust to metadata ordering):
    //   X:33554432  W1:4194304(first)  W2:4194304(second)  b1:16384  b2:4096  ids:131072
    const float *X = 0, *W1 = 0, *B1 = 0, *W2 = 0, *B2 = 0;
    const void  *IDS = 0;
    for (int i = 0; i < n_in; i++) {
        switch (in_sizes[i]) {
            case 33554432: X = (const float*)d_in[i]; break;
            case 4194304:  if (!W1) W1 = (const float*)d_in[i];
                           else     W2 = (const float*)d_in[i];
                           break;
            case 16384:    B1 = (const float*)d_in[i]; break;
            case 4096:     B2 = (const float*)d_in[i]; break;
            case 131072:   IDS = d_in[i]; break;
            default: break;
        }
    }
    float* Y = (float*)d_out;

    cudaFuncSetAttribute(k_moe, cudaFuncAttributeMaxDynamicSharedMemorySize, SMEM_BYTES);

    k_detect<<<1, 256>>>((const long long*)IDS);
    k_zero<<<1, 32>>>();
    k_count<<<256, 256>>>(IDS);
    k_scan<<<1, 32>>>();
    k_scatter<<<256, 256>>>(IDS);
    k_moe<<<GRID, 256, SMEM_BYTES>>>(X, W1, B1, W2, B2, Y);
}

// round 4
// speedup vs baseline: 3.8314x; 3.8314x over previous
#include <cuda_runtime.h>
#include <cstdint>
#include <cstddef>

// Problem constants
#define NF   131072
#define INS  256
#define HID  1024
#define OUTS 256
#define NE   16
#define TM   128                 // tokens per CTA tile
#define HC   32                  // hidden chunk per iteration
#define NCHUNK (HID / HC)        // 32
#define GRID2 (NF / TM + NE)     // 1040

typedef unsigned int u32;

// ---------------- routing scratch ----------------
__device__ int g_cnt[NE];
__device__ int g_off[NE + 1];
__device__ int g_cur[NE];
__device__ int g_tile[NE + 1];
__device__ int g_perm[NF];
__device__ int g_ids_is64;

// ---------------- id dtype probe ----------------
__global__ void k_detect(const long long* __restrict__ ids) {
    __shared__ int bad;
    if (threadIdx.x == 0) bad = 0;
    __syncthreads();
    for (int i = threadIdx.x; i < 4096; i += 256) {
        unsigned long long v = (unsigned long long)ids[i];
        if (v > 15ULL) bad = 1;
    }
    __syncthreads();
    if (threadIdx.x == 0) g_ids_is64 = bad ? 0 : 1;
}

__device__ __forceinline__ int get_id(const void* ids, int i, int is64) {
    int e = is64 ? (int)((const long long*)ids)[i] : ((const int*)ids)[i];
    return e & 15;
}

// ---------------- routing ----------------
__global__ void k_zero() {
    if (threadIdx.x < NE) g_cnt[threadIdx.x] = 0;
}

__global__ void k_count(const void* __restrict__ ids) {
    __shared__ int h[NE];
    int tid = threadIdx.x;
    if (tid < NE) h[tid] = 0;
    __syncthreads();
    int is64 = g_ids_is64;
    int base = blockIdx.x * 512;
    atomicAdd(&h[get_id(ids, base + tid, is64)], 1);
    atomicAdd(&h[get_id(ids, base + 256 + tid, is64)], 1);
    __syncthreads();
    if (tid < NE) atomicAdd(&g_cnt[tid], h[tid]);
}

__global__ void k_scan() {
    if (threadIdx.x == 0) {
        int o = 0, t = 0;
        for (int e = 0; e < NE; e++) {
            g_off[e] = o; g_cur[e] = o; g_tile[e] = t;
            o += g_cnt[e];
            t += (g_cnt[e] + TM - 1) / TM;
        }
        g_off[NE] = o; g_tile[NE] = t;
    }
}

__global__ void k_scatter(const void* __restrict__ ids) {
    __shared__ int h[NE], bm[NE];
    int tid = threadIdx.x;
    if (tid < NE) h[tid] = 0;
    __syncthreads();
    int is64 = g_ids_is64;
    int base = blockIdx.x * 512;
    int e0 = get_id(ids, base + tid, is64);
    int e1 = get_id(ids, base + 256 + tid, is64);
    atomicAdd(&h[e0], 1);
    atomicAdd(&h[e1], 1);
    __syncthreads();
    if (tid < NE) { bm[tid] = atomicAdd(&g_cur[tid], h[tid]); h[tid] = 0; }
    __syncthreads();
    int r0 = atomicAdd(&h[e0], 1); g_perm[bm[e0] + r0] = base + tid;
    int r1 = atomicAdd(&h[e1], 1); g_perm[bm[e1] + r1] = base + 256 + tid;
}

// ---------------- helpers ----------------
__device__ __forceinline__ u32 f2tf32(float f) {  // round-to-nearest tf32 (zero-mean error)
    u32 u; asm("cvt.rna.tf32.f32 %0, %1;" : "=r"(u) : "f"(f)); return u;
}

// m16n8k8 tf32 MMA (legacy tensor path — valid on plain sm_103 target)
__device__ __forceinline__ void mma8(float* d, const u32* a, const u32* b) {
    asm volatile("mma.sync.aligned.m16n8k8.row.col.f32.tf32.tf32.f32 "
        "{%0,%1,%2,%3}, {%4,%5,%6,%7}, {%8,%9}, {%0,%1,%2,%3};"
        : "+f"(d[0]), "+f"(d[1]), "+f"(d[2]), "+f"(d[3])
        : "r"(a[0]), "r"(a[1]), "r"(a[2]), "r"(a[3]), "r"(b[0]), "r"(b[1]));
}

// ---------------- SMEM layout (u32 element offsets) ----------------
// sX  [128][260]  tf32 X tile            133120 B   bank: (4*gid+tig) distinct
// sW1 [256][40]   tf32 W1 chunk [k][n]    40960 B   bank: (8*tig+gid) distinct
// sW2 [32][264]   tf32 W2 chunk [k][n]    33792 B   bank: (8*tig+gid) distinct
// sH  [128][40]   tf32 h tile  [r][k]     20480 B
// sb1[32], sb2[256], toks[128]
#define XS   260
#define W1S  40
#define W2S  264
#define HS   40
#define OFF_X    0
#define OFF_W1   (128 * XS)                  // 33280
#define OFF_W2   (OFF_W1 + 256 * W1S)        // 43520
#define OFF_H    (OFF_W2 + 32 * W2S)         // 51968
#define OFF_B1   (OFF_H + 128 * HS)          // 57088
#define OFF_B2   (OFF_B1 + 32)               // 57120
#define OFF_TOKS (OFF_B2 + 256)              // 57376
#define SMEM_U32 (OFF_TOKS + 128)            // 57504
#define SMEM_BYTES (SMEM_U32 * 4)            // 230016

__global__ void __launch_bounds__(256, 1)
k_mlp(const float* __restrict__ X,  const float* __restrict__ W1,
      const float* __restrict__ B1v, const float* __restrict__ W2,
      const float* __restrict__ B2v, float* __restrict__ Y)
{
    extern __shared__ u32 smu[];
    u32*   sX  = smu + OFF_X;
    u32*   sW1 = smu + OFF_W1;
    u32*   sW2 = smu + OFF_W2;
    u32*   sH  = smu + OFF_H;
    float* sb1 = (float*)(smu + OFF_B1);
    float* sb2 = (float*)(smu + OFF_B2);
    int*   toks = (int*)(smu + OFF_TOKS);

    int tid  = threadIdx.x;
    int wid  = tid >> 5;
    int lane = tid & 31;
    int gid  = lane >> 2;     // 0..7
    int tig  = lane & 3;      // 0..3
    int r0   = wid * 16;      // warp's token rows [r0, r0+16)

    int bid = blockIdx.x;
    if (bid >= g_tile[NE]) return;
    int e = 0;
    while (bid >= g_tile[e + 1]) e++;
    int goff = g_off[e];
    int cnt  = g_off[e + 1] - goff;
    int t0   = (bid - g_tile[e]) * TM;
    int vcnt = min(TM, cnt - t0);

    if (tid < TM) {
        int slot = t0 + tid;
        if (slot >= cnt) slot = cnt - 1;   // duplicate-pad tail; stores masked later
        toks[tid] = g_perm[goff + slot];
    }
    sb2[tid] = B2v[(size_t)e * OUTS + tid];
    __syncthreads();

    const float* w1e = W1  + (size_t)e * INS * HID;
    const float* w2e = W2  + (size_t)e * HID * OUTS;
    const float* b1e = B1v + (size_t)e * HID;

    // ---- Load X tile (tf32-rounded) ----
    #pragma unroll 4
    for (int i = 0; i < 32; i++) {
        int g  = i * 256 + tid;       // 8192 float4 slots
        int r  = g >> 6;              // 0..127
        int c4 = g & 63;
        float4 v = *(const float4*)(X + (size_t)toks[r] * INS + c4 * 4);
        uint4 t4 = { f2tf32(v.x), f2tf32(v.y), f2tf32(v.z), f2tf32(v.w) };
        *(uint4*)&sX[r * XS + c4 * 4] = t4;
    }

    float yacc[32][4];
    #pragma unroll
    for (int nt = 0; nt < 32; nt++)
        #pragma unroll
        for (int j = 0; j < 4; j++) yacc[nt][j] = 0.0f;

    for (int n = 0; n < NCHUNK; n++) {
        int h0 = n * HC;
        __syncthreads();   // prior GEMM2 done with sW2/sH; (iter0: X/toks ready)

        // ---- Load W1 chunk [256 k][32 n] ----
        #pragma unroll
        for (int i = 0; i < 8; i++) {
            int g  = i * 256 + tid;   // 2048 float4
            int r  = g >> 3;          // k row 0..255
            int c4 = g & 7;
            float4 v = *(const float4*)(w1e + (size_t)r * HID + h0 + c4 * 4);
            uint4 t4 = { f2tf32(v.x), f2tf32(v.y), f2tf32(v.z), f2tf32(v.w) };
            *(uint4*)&sW1[r * W1S + c4 * 4] = t4;
        }
        // ---- Load W2 chunk [32 k][256 n] ----
        #pragma unroll
        for (int i = 0; i < 8; i++) {
            int g  = i * 256 + tid;   // 2048 float4
            int r  = g >> 6;          // 0..31
            int c4 = g & 63;
            float4 v = *(const float4*)(w2e + (size_t)(h0 + r) * OUTS + c4 * 4);
            uint4 t4 = { f2tf32(v.x), f2tf32(v.y), f2tf32(v.z), f2tf32(v.w) };
            *(uint4*)&sW2[r * W2S + c4 * 4] = t4;
        }
        if (tid < HC) sb1[tid] = b1e[h0 + tid];
        __syncthreads();

        // ---- GEMM1: h[16 rows][32] = X[16][256] @ W1chunk ----
        float acc1[4][4];
        #pragma unroll
        for (int nt = 0; nt < 4; nt++)
            #pragma unroll
            for (int j = 0; j < 4; j++) acc1[nt][j] = 0.0f;

        {
            const u32* x0 = sX + (r0 + gid) * XS;
            const u32* x1 = sX + (r0 + gid + 8) * XS;
            #pragma unroll 4
            for (int kt = 0; kt < 32; kt++) {
                int k0 = kt * 8;
                u32 a[4] = { x0[k0 + tig], x1[k0 + tig], x0[k0 + tig + 4], x1[k0 + tig + 4] };
                const u32* bwl = sW1 + (k0 + tig) * W1S + gid;
                const u32* bwh = sW1 + (k0 + tig + 4) * W1S + gid;
                #pragma unroll
                for (int nt = 0; nt < 4; nt++) {
                    u32 b[2] = { bwl[nt * 8], bwh[nt * 8] };
                    mma8(acc1[nt], a, b);
                }
            }
        }

        // ---- Epilogue: relu(h + b1) -> tf32 -> sH ----
        #pragma unroll
        for (int nt = 0; nt < 4; nt++) {
            int c = nt * 8 + 2 * tig;
            float ba = sb1[c], bb = sb1[c + 1];
            uint2 lo = { f2tf32(fmaxf(acc1[nt][0] + ba, 0.0f)),
                         f2tf32(fmaxf(acc1[nt][1] + bb, 0.0f)) };
            uint2 hi = { f2tf32(fmaxf(acc1[nt][2] + ba, 0.0f)),
                         f2tf32(fmaxf(acc1[nt][3] + bb, 0.0f)) };
            *(uint2*)&sH[(r0 + gid) * HS + c]     = lo;
            *(uint2*)&sH[(r0 + gid + 8) * HS + c] = hi;
        }
        __syncthreads();   // sH complete for all warps

        // ---- GEMM2: Y[16][256] += h[16][32] @ W2chunk ----
        #pragma unroll
        for (int kt = 0; kt < 4; kt++) {
            int k0 = kt * 8;
            u32 a[4] = { sH[(r0 + gid) * HS + k0 + tig],
                         sH[(r0 + gid + 8) * HS + k0 + tig],
                         sH[(r0 + gid) * HS + k0 + tig + 4],
                         sH[(r0 + gid + 8) * HS + k0 + tig + 4] };
            const u32* bwl = sW2 + (k0 + tig) * W2S + gid;
            const u32* bwh = sW2 + (k0 + tig + 4) * W2S + gid;
            #pragma unroll
            for (int nt = 0; nt < 32; nt++) {
                u32 b[2] = { bwl[nt * 8], bwh[nt * 8] };
                mma8(yacc[nt], a, b);
            }
        }
    }

    // ---- Final: Y + b2, masked scatter store ----
    {
        int  rA = r0 + gid, rB = r0 + gid + 8;
        bool vA = rA < vcnt, vB = rB < vcnt;
        float* yA = Y + (size_t)toks[rA] * OUTS;
        float* yB = Y + (size_t)toks[rB] * OUTS;
        #pragma unroll
        for (int nt = 0; nt < 32; nt++) {
            int c = nt * 8 + 2 * tig;
            float ba = sb2[c], bb = sb2[c + 1];
            if (vA) { float2 v = { yacc[nt][0] + ba, yacc[nt][1] + bb }; *(float2*)(yA + c) = v; }
            if (vB) { float2 v = { yacc[nt][2] + ba, yacc[nt][3] + bb }; *(float2*)(yB + c) = v; }
        }
    }
}

// ---------------- launch ----------------
extern "C" void kernel_launch(void* const* d_in, const int* in_sizes, int n_in,
                              void* d_out, int out_size)
{
    (void)out_size;
    const float *X = 0, *W1 = 0, *B1 = 0, *W2 = 0, *B2 = 0;
    const void  *IDS = 0;
    for (int i = 0; i < n_in; i++) {
        switch (in_sizes[i]) {
            case 33554432: X = (const float*)d_in[i]; break;
            case 4194304:  if (!W1) W1 = (const float*)d_in[i];
                           else     W2 = (const float*)d_in[i];
                           break;
            case 16384:    B1 = (const float*)d_in[i]; break;
            case 4096:     B2 = (const float*)d_in[i]; break;
            case 131072:   IDS = d_in[i]; break;
            default: break;
        }
    }
    float* Y = (float*)d_out;

    cudaFuncSetAttribute(k_mlp, cudaFuncAttributeMaxDynamicSharedMemorySize, SMEM_BYTES);

    k_detect<<<1, 256>>>((const long long*)IDS);
    k_zero<<<1, 32>>>();
    k_count<<<256, 256>>>(IDS);
    k_scan<<<1, 32>>>();
    k_scatter<<<256, 256>>>(IDS);
    k_mlp<<<GRID2, 256, SMEM_BYTES>>>(X, W1, B1, W2, B2, Y);
}

// round 5
// speedup vs baseline: 4.8582x; 1.2680x over previous
#include <cuda_runtime.h>
#include <cstdint>
#include <cstddef>

// Problem constants
#define NF   131072
#define INS  256
#define HID  1024
#define OUTS 256
#define NE   16
#define TM   128                 // tokens per CTA tile
#define HC   32                  // hidden chunk per iteration
#define NCHUNK (HID / HC)        // 32
#define GRID2 (NF / TM + NE)     // 1040

typedef unsigned int u32;

// ---------------- routing scratch ----------------
__device__ int g_cnt[NE];
__device__ int g_off[NE + 1];
__device__ int g_cur[NE];
__device__ int g_tile[NE + 1];
__device__ int g_perm[NF];
__device__ int g_ids_is64;

// ---------------- id dtype probe ----------------
__global__ void k_detect(const long long* __restrict__ ids) {
    __shared__ int bad;
    if (threadIdx.x == 0) bad = 0;
    __syncthreads();
    for (int i = threadIdx.x; i < 4096; i += 256) {
        unsigned long long v = (unsigned long long)ids[i];
        if (v > 15ULL) bad = 1;
    }
    __syncthreads();
    if (threadIdx.x == 0) g_ids_is64 = bad ? 0 : 1;
}

__device__ __forceinline__ int get_id(const void* ids, int i, int is64) {
    int e = is64 ? (int)((const long long*)ids)[i] : ((const int*)ids)[i];
    return e & 15;
}

// ---------------- routing ----------------
__global__ void k_zero() {
    if (threadIdx.x < NE) g_cnt[threadIdx.x] = 0;
}

__global__ void k_count(const void* __restrict__ ids) {
    __shared__ int h[NE];
    int tid = threadIdx.x;
    if (tid < NE) h[tid] = 0;
    __syncthreads();
    int is64 = g_ids_is64;
    int base = blockIdx.x * 512;
    atomicAdd(&h[get_id(ids, base + tid, is64)], 1);
    atomicAdd(&h[get_id(ids, base + 256 + tid, is64)], 1);
    __syncthreads();
    if (tid < NE) atomicAdd(&g_cnt[tid], h[tid]);
}

__global__ void k_scan() {
    if (threadIdx.x == 0) {
        int o = 0, t = 0;
        for (int e = 0; e < NE; e++) {
            g_off[e] = o; g_cur[e] = o; g_tile[e] = t;
            o += g_cnt[e];
            t += (g_cnt[e] + TM - 1) / TM;
        }
        g_off[NE] = o; g_tile[NE] = t;
    }
}

__global__ void k_scatter(const void* __restrict__ ids) {
    __shared__ int h[NE], bm[NE];
    int tid = threadIdx.x;
    if (tid < NE) h[tid] = 0;
    __syncthreads();
    int is64 = g_ids_is64;
    int base = blockIdx.x * 512;
    int e0 = get_id(ids, base + tid, is64);
    int e1 = get_id(ids, base + 256 + tid, is64);
    atomicAdd(&h[e0], 1);
    atomicAdd(&h[e1], 1);
    __syncthreads();
    if (tid < NE) { bm[tid] = atomicAdd(&g_cur[tid], h[tid]); h[tid] = 0; }
    __syncthreads();
    int r0 = atomicAdd(&h[e0], 1); g_perm[bm[e0] + r0] = base + tid;
    int r1 = atomicAdd(&h[e1], 1); g_perm[bm[e1] + r1] = base + 256 + tid;
}

// ---------------- helpers ----------------
__device__ __forceinline__ u32 f2tf32(float f) {  // round-to-nearest tf32 (zero-mean error)
    u32 u; asm("cvt.rna.tf32.f32 %0, %1;" : "=r"(u) : "f"(f)); return u;
}
__device__ __forceinline__ u32 smem_u32(const void* p) {
    u32 a;
    asm("{ .reg .u64 t; cvta.to.shared.u64 t, %1; cvt.u32.u64 %0, t; }" : "=r"(a) : "l"(p));
    return a;
}
__device__ __forceinline__ void cpa16(u32 dst, const void* src) {
    asm volatile("cp.async.cg.shared.global [%0], [%1], 16;" :: "r"(dst), "l"(src));
}
#define CPA_COMMIT() asm volatile("cp.async.commit_group;" ::: "memory")
#define CPA_WAIT1()  asm volatile("cp.async.wait_group 1;" ::: "memory")

// m16n8k8 tf32 MMA (legacy tensor path — valid on plain sm_103 target)
__device__ __forceinline__ void mma8(float* d, const u32* a, const u32* b) {
    asm volatile("mma.sync.aligned.m16n8k8.row.col.f32.tf32.tf32.f32 "
        "{%0,%1,%2,%3}, {%4,%5,%6,%7}, {%8,%9}, {%0,%1,%2,%3};"
        : "+f"(d[0]), "+f"(d[1]), "+f"(d[2]), "+f"(d[3])
        : "r"(a[0]), "r"(a[1]), "r"(a[2]), "r"(a[3]), "r"(b[0]), "r"(b[1]));
}

// ---------------- SMEM layout (u32 element offsets) ----------------
// sX   [128][260]  tf32 X tile (padded; banks 4*gid+tig distinct)   133120 B
// sW1r [256][32]   raw fp32 W1 chunk, k-XOR swizzled                 32768 B
// sW2r [32][256]   raw fp32 W2 chunk, k-XOR swizzled                 32768 B
// sH   [128][36]   tf32 h tile (pad; banks 4*gid+tig distinct)       18432 B
// sb2[256], toks[128]
#define XS   260
#define HSd  36
#define OFF_X    0
#define OFF_W1   33280
#define OFF_W2   41472
#define OFF_H    49664
#define OFF_B2   54272
#define OFF_TOKS 54528
#define SMEM_U32 54656
#define SMEM_BYTES (SMEM_U32 * 4)    // 218624

__global__ void __launch_bounds__(256, 1)
k_mlp(const float* __restrict__ X,  const float* __restrict__ W1,
      const float* __restrict__ B1v, const float* __restrict__ W2,
      const float* __restrict__ B2v, float* __restrict__ Y)
{
    extern __shared__ u32 smu[];
    u32*   sX   = smu + OFF_X;
    u32*   sW1r = smu + OFF_W1;
    u32*   sW2r = smu + OFF_W2;
    u32*   sH   = smu + OFF_H;
    float* sb2  = (float*)(smu + OFF_B2);
    int*   toks = (int*)(smu + OFF_TOKS);
    u32 sbase = smem_u32(smu);

    int tid  = threadIdx.x;
    int wid  = tid >> 5;
    int lane = tid & 31;
    int gid  = lane >> 2;      // 0..7
    int tig  = lane & 3;       // 0..3
    // GEMM1 split: 4 m-groups x 2 n-groups (warp: 32 rows x 16 n)
    int m0  = (wid & 3) * 32;
    int n0  = (wid >> 2) * 16;
    // GEMM2 split: 2 m-groups x 4 n-groups (warp: 64 rows x 64 n)
    int m02 = (wid & 1) * 64;
    int n02 = (wid >> 1) * 64;
    u32 swz = (u32)(tig << 3);  // B-read swizzle (k&3 == tig always, k0 ≡ 0 mod 8)

    int bid = blockIdx.x;
    if (bid >= g_tile[NE]) return;
    int e = 0;
    while (bid >= g_tile[e + 1]) e++;
    int goff = g_off[e];
    int cnt  = g_off[e + 1] - goff;
    int t0   = (bid - g_tile[e]) * TM;
    int vcnt = min(TM, cnt - t0);

    const float* w1e = W1  + (size_t)e * INS * HID;
    const float* w2e = W2  + (size_t)e * HID * OUTS;
    const float* b1e = B1v + (size_t)e * HID;

    // ---- Prologue: issue cp.async for W1(0), W2(0) (raw fp32, k-XOR swizzle) ----
    {
        #pragma unroll
        for (int i = 0; i < 8; i++) {           // W1 chunk 0: [256 k][32 n]
            int idx = i * 256 + tid;
            int k = idx >> 3, c = idx & 7;
            int c2 = c ^ ((k & 3) << 1);
            cpa16(sbase + (OFF_W1 + k * 32 + c2 * 4) * 4, w1e + (size_t)k * HID + c * 4);
        }
        CPA_COMMIT();
        #pragma unroll
        for (int i = 0; i < 8; i++) {           // W2 chunk 0: [32 k][256 n]
            int idx = i * 256 + tid;
            int k = idx >> 6, c = idx & 63;
            int c2 = c ^ ((k & 3) << 1);
            cpa16(sbase + (OFF_W2 + k * 256 + c2 * 4) * 4, w2e + (size_t)k * OUTS + c * 4);
        }
        CPA_COMMIT();
    }

    if (tid < TM) {
        int slot = t0 + tid;
        if (slot >= cnt) slot = cnt - 1;   // duplicate-pad tail; stores masked later
        toks[tid] = g_perm[goff + slot];
    }
    sb2[tid] = B2v[(size_t)e * OUTS + tid];
    __syncthreads();

    // ---- Load X tile (tf32-rounded, padded layout) ----
    #pragma unroll 4
    for (int i = 0; i < 32; i++) {
        int g  = i * 256 + tid;       // 8192 float4 slots
        int r  = g >> 6;              // 0..127
        int c4 = g & 63;
        float4 v = *(const float4*)(X + (size_t)toks[r] * INS + c4 * 4);
        uint4 t4 = { f2tf32(v.x), f2tf32(v.y), f2tf32(v.z), f2tf32(v.w) };
        *(uint4*)&sX[r * XS + c4 * 4] = t4;
    }

    float yacc[4][8][4];
    #pragma unroll
    for (int mt = 0; mt < 4; mt++)
        #pragma unroll
        for (int nb = 0; nb < 8; nb++)
            #pragma unroll
            for (int j = 0; j < 4; j++) yacc[mt][nb][j] = 0.0f;

    for (int n = 0; n < NCHUNK; n++) {
        int h0 = n * HC;

        CPA_WAIT1();        // W1(n) complete (own); W2(n) may still be in flight
        __syncthreads();    // publish W1(n); everyone past GEMM2(n-1)

        // b1 prefetch (consumed in epilogue, latency hidden by GEMM1)
        float bv0 = b1e[h0 + n0 + 2 * tig];
        float bv1 = b1e[h0 + n0 + 2 * tig + 1];
        float bv2 = b1e[h0 + n0 + 8 + 2 * tig];
        float bv3 = b1e[h0 + n0 + 8 + 2 * tig + 1];

        // ---- GEMM1: h[32 rows][16 n] per warp = X @ W1chunk ----
        float acc1[2][2][4];
        #pragma unroll
        for (int mt = 0; mt < 2; mt++)
            #pragma unroll
            for (int nb = 0; nb < 2; nb++)
                #pragma unroll
                for (int j = 0; j < 4; j++) acc1[mt][nb][j] = 0.0f;

        #pragma unroll 4
        for (int kt = 0; kt < 32; kt++) {
            int k0 = kt * 8;
            u32 a[2][4];
            #pragma unroll
            for (int mt = 0; mt < 2; mt++) {
                int r = m0 + 16 * mt + gid;
                a[mt][0] = sX[r * XS + k0 + tig];
                a[mt][1] = sX[(r + 8) * XS + k0 + tig];
                a[mt][2] = sX[r * XS + k0 + tig + 4];
                a[mt][3] = sX[(r + 8) * XS + k0 + tig + 4];
            }
            #pragma unroll
            for (int nb = 0; nb < 2; nb++) {
                u32 ci = (u32)(n0 + 8 * nb + gid) ^ swz;
                u32 r0w = sW1r[(k0 + tig) * 32 + ci];
                u32 r1w = sW1r[(k0 + tig + 4) * 32 + ci];
                u32 b[2] = { f2tf32(__uint_as_float(r0w)), f2tf32(__uint_as_float(r1w)) };
                mma8(acc1[0][nb], a[0], b);
                mma8(acc1[1][nb], a[1], b);
            }
        }

        // ---- Epilogue A: relu(h + b1) -> tf32 -> sH ----
        #pragma unroll
        for (int mt = 0; mt < 2; mt++) {
            int r = m0 + 16 * mt + gid;
            #pragma unroll
            for (int nb = 0; nb < 2; nb++) {
                int c = n0 + 8 * nb + 2 * tig;
                float ba = nb ? bv2 : bv0;
                float bb = nb ? bv3 : bv1;
                uint2 lo = { f2tf32(fmaxf(acc1[mt][nb][0] + ba, 0.0f)),
                             f2tf32(fmaxf(acc1[mt][nb][1] + bb, 0.0f)) };
                uint2 hi = { f2tf32(fmaxf(acc1[mt][nb][2] + ba, 0.0f)),
                             f2tf32(fmaxf(acc1[mt][nb][3] + bb, 0.0f)) };
                *(uint2*)&sH[r * HSd + c]       = lo;
                *(uint2*)&sH[(r + 8) * HSd + c] = hi;
            }
        }
        __syncthreads();    // sW1 free; sH visible to all warps

        // ---- Issue W1(n+1) (overlaps GEMM2(n)) ----
        if (n + 1 < NCHUNK) {
            int h1 = h0 + HC;
            #pragma unroll
            for (int i = 0; i < 8; i++) {
                int idx = i * 256 + tid;
                int k = idx >> 3, c = idx & 7;
                int c2 = c ^ ((k & 3) << 1);
                cpa16(sbase + (OFF_W1 + k * 32 + c2 * 4) * 4,
                      w1e + (size_t)k * HID + h1 + c * 4);
            }
        }
        CPA_COMMIT();

        CPA_WAIT1();        // W2(n) complete (own); W1(n+1) in flight
        __syncthreads();    // publish W2(n)

        // ---- GEMM2: Y[64 rows][64 n] per warp += h @ W2chunk ----
        #pragma unroll
        for (int kt = 0; kt < 4; kt++) {
            int k0 = kt * 8;
            u32 ah[4][4];
            #pragma unroll
            for (int mt = 0; mt < 4; mt++) {
                int r = m02 + 16 * mt + gid;
                ah[mt][0] = sH[r * HSd + k0 + tig];
                ah[mt][1] = sH[(r + 8) * HSd + k0 + tig];
                ah[mt][2] = sH[r * HSd + k0 + tig + 4];
                ah[mt][3] = sH[(r + 8) * HSd + k0 + tig + 4];
            }
            #pragma unroll
            for (int nb = 0; nb < 8; nb++) {
                u32 ci = (u32)(n02 + 8 * nb + gid) ^ swz;
                u32 r0w = sW2r[(k0 + tig) * 256 + ci];
                u32 r1w = sW2r[(k0 + tig + 4) * 256 + ci];
                u32 b[2] = { f2tf32(__uint_as_float(r0w)), f2tf32(__uint_as_float(r1w)) };
                mma8(yacc[0][nb], ah[0], b);
                mma8(yacc[1][nb], ah[1], b);
                mma8(yacc[2][nb], ah[2], b);
                mma8(yacc[3][nb], ah[3], b);
            }
        }
        __syncthreads();    // sW2 free

        // ---- Issue W2(n+1) (overlaps next GEMM1) ----
        if (n + 1 < NCHUNK) {
            int h1 = h0 + HC;
            #pragma unroll
            for (int i = 0; i < 8; i++) {
                int idx = i * 256 + tid;
                int k = idx >> 6, c = idx & 63;
                int c2 = c ^ ((k & 3) << 1);
                cpa16(sbase + (OFF_W2 + k * 256 + c2 * 4) * 4,
                      w2e + (size_t)(h1 + k) * OUTS + c * 4);
            }
        }
        CPA_COMMIT();
    }

    // ---- Final: Y + b2, masked scatter store ----
    #pragma unroll
    for (int mt = 0; mt < 4; mt++) {
        int  rA = m02 + 16 * mt + gid, rB = rA + 8;
        bool vA = rA < vcnt, vB = rB < vcnt;
        float* yA = Y + (size_t)toks[rA] * OUTS;
        float* yB = Y + (size_t)toks[rB] * OUTS;
        #pragma unroll
        for (int nb = 0; nb < 8; nb++) {
            int c = n02 + 8 * nb + 2 * tig;
            float ba = sb2[c], bb = sb2[c + 1];
            if (vA) { float2 v = { yacc[mt][nb][0] + ba, yacc[mt][nb][1] + bb }; *(float2*)(yA + c) = v; }
            if (vB) { float2 v = { yacc[mt][nb][2] + ba, yacc[mt][nb][3] + bb }; *(float2*)(yB + c) = v; }
        }
    }
}

// ---------------- launch ----------------
extern "C" void kernel_launch(void* const* d_in, const int* in_sizes, int n_in,
                              void* d_out, int out_size)
{
    (void)out_size;
    const float *X = 0, *W1 = 0, *B1 = 0, *W2 = 0, *B2 = 0;
    const void  *IDS = 0;
    for (int i = 0; i < n_in; i++) {
        switch (in_sizes[i]) {
            case 33554432: X = (const float*)d_in[i]; break;
            case 4194304:  if (!W1) W1 = (const float*)d_in[i];
                           else     W2 = (const float*)d_in[i];
                           break;
            case 16384:    B1 = (const float*)d_in[i]; break;
            case 4096:     B2 = (const float*)d_in[i]; break;
            case 131072:   IDS = d_in[i]; break;
            default: break;
        }
    }
    float* Y = (float*)d_out;

    cudaFuncSetAttribute(k_mlp, cudaFuncAttributeMaxDynamicSharedMemorySize, SMEM_BYTES);

    k_detect<<<1, 256>>>((const long long*)IDS);
    k_zero<<<1, 32>>>();
    k_count<<<256, 256>>>(IDS);
    k_scan<<<1, 32>>>();
    k_scatter<<<256, 256>>>(IDS);
    k_mlp<<<GRID2, 256, SMEM_BYTES>>>(X, W1, B1, W2, B2, Y);
}